// round 9
// baseline (speedup 1.0000x reference)
#include <cuda_runtime.h>
#include <math_constants.h>
#include <cstdint>

#define NN 50000
#define NE 800000
#define F_IN 256
#define F_EDGE 64
#define HH 4
#define DD 64
#define HD 256
#define NEG_SLOPE 0.2f

// ---------------- scratch (device globals; no allocation allowed) ----------
__device__ float g_feat[(size_t)NN * HD];    // h @ W_fc^T
__device__ float g_rst[(size_t)NN * HD];     // unnormalized aggregated messages
__device__ float g_el[NN * HH];
__device__ float g_er[NN * HH];
__device__ float g_e[(size_t)NE * HH];       // leaky-relu'd logits
__device__ float g_m[NN * HH];               // segment max (init 0xFF bytes)
__device__ float g_denom[NN * HH];           // segment sum of exp
__device__ float g_deg[NN];                  // in-degree
__device__ float g_v[HH * F_EDGE];           // attn_e folded into W_edge

// ---------------- helpers --------------------------------------------------
// Float atomic max via int/uint ordering trick.
// Strictly-positive -> signed int max; zero/negative -> unsigned min.
// Valid identity element: 0xFFFFFFFF (int -1 / uint MAX), set via memset 0xFF.
__device__ __forceinline__ void atomicMaxFloat(float* addr, float v) {
    if (v > 0.0f) atomicMax((int*)addr, __float_as_int(v));
    else          atomicMin((unsigned int*)addr, __float_as_uint(v));
}

// ---------------- K0: fold attn_e into W_edge ------------------------------
__global__ void compute_ve(const float* __restrict__ W_edge,
                           const float* __restrict__ attn_e) {
    int tid = threadIdx.x;            // 256 threads: (h, c)
    int h = tid >> 6, c = tid & 63;
    float s = 0.0f;
    #pragma unroll 8
    for (int d = 0; d < DD; d++)
        s += attn_e[h * DD + d] * W_edge[(h * DD + d) * F_EDGE + c];
    g_v[tid] = s;
}

// ---------------- K2: fused GEMM  C[N,512] = h @ [W_fc | W_res]^T ----------
// 128x128 tile, BK=16, 256 threads, 8x8 per thread, double-buffered SMEM.
// blockIdx.y: 0,1 -> feat (cols 0..255) + fused el/er epilogue,
//             2,3 -> res written into d_out.
// Head alignment: bn=0 covers heads 0,1; bn=1 covers heads 2,3 (D=64).
__global__ void __launch_bounds__(256) fused_gemm(
        const float* __restrict__ A,      // h [n,256]
        const float* __restrict__ Wfc,    // [256,256]
        const float* __restrict__ Wres,   // [256,256]
        const float* __restrict__ attn_l, // [4,64] flat 256
        const float* __restrict__ attn_r, // [4,64] flat 256
        float* __restrict__ d_out, int n) {
    __shared__ float As[2][16][128];
    __shared__ float Bs[2][16][128];
    __shared__ float sal[128], sar[128];

    const int bm = blockIdx.x, bn = blockIdx.y;
    const float* W = (bn < 2) ? Wfc : Wres;
    const int wrow0 = (bn & 1) * 128;          // row offset within W
    const int row0 = bm * 128;
    const int tid = threadIdx.x;
    const int tx = tid & 15, ty = tid >> 4;

    const int lr = tid >> 2;                   // 0..63
    const int lc = (tid & 3) * 4;              // 0,4,8,12

    float acc[8][8] = {};

    auto load_tiles = [&](int k0, int buf) {
        #pragma unroll
        for (int r = 0; r < 2; r++) {
            int m = lr + r * 64;
            int grow = row0 + m;
            float4 v = make_float4(0.f, 0.f, 0.f, 0.f);
            if (grow < n)
                v = *(const float4*)(A + (size_t)grow * 256 + k0 + lc);
            As[buf][lc + 0][m] = v.x; As[buf][lc + 1][m] = v.y;
            As[buf][lc + 2][m] = v.z; As[buf][lc + 3][m] = v.w;
        }
        #pragma unroll
        for (int r = 0; r < 2; r++) {
            int nn2 = lr + r * 64;
            float4 v = *(const float4*)(W + (size_t)(wrow0 + nn2) * 256 + k0 + lc);
            Bs[buf][lc + 0][nn2] = v.x; Bs[buf][lc + 1][nn2] = v.y;
            Bs[buf][lc + 2][nn2] = v.z; Bs[buf][lc + 3][nn2] = v.w;
        }
    };

    if (bn < 2 && tid < 128) {                 // cache this block's attn slice
        sal[tid] = attn_l[bn * 128 + tid];
        sar[tid] = attn_r[bn * 128 + tid];
    }

    load_tiles(0, 0);
    __syncthreads();

    int buf = 0;
    for (int k0 = 0; k0 < 256; k0 += 16) {
        int nbuf = buf ^ 1;
        if (k0 + 16 < 256)
            load_tiles(k0 + 16, nbuf);         // prefetch next tile into alt buffer
        #pragma unroll
        for (int k = 0; k < 16; k++) {
            float ra[8], rb[8];
            *(float4*)&ra[0] = *(const float4*)&As[buf][k][ty * 8];
            *(float4*)&ra[4] = *(const float4*)&As[buf][k][ty * 8 + 4];
            *(float4*)&rb[0] = *(const float4*)&Bs[buf][k][tx * 8];
            *(float4*)&rb[4] = *(const float4*)&Bs[buf][k][tx * 8 + 4];
            #pragma unroll
            for (int i = 0; i < 8; i++)
                #pragma unroll
                for (int j = 0; j < 8; j++)
                    acc[i][j] += ra[i] * rb[j];
        }
        __syncthreads();                       // compute(buf) done + loads(nbuf) visible
        buf = nbuf;
    }

    float* dstbuf = (bn < 2) ? g_feat : d_out;
    const int colbase = (bn & 1) * 128 + tx * 8;
    #pragma unroll
    for (int i = 0; i < 8; i++) {
        int grow = row0 + ty * 8 + i;
        if (grow < n) {
            float* p = dstbuf + (size_t)grow * 256 + colbase;
            *(float4*)p       = make_float4(acc[i][0], acc[i][1], acc[i][2], acc[i][3]);
            *(float4*)(p + 4) = make_float4(acc[i][4], acc[i][5], acc[i][6], acc[i][7]);
        }
    }

    // ---- fused el/er epilogue (feat blocks only) ----
    // thread's 8 cols (tx*8..tx*8+7, local) lie entirely in head bn*2 + tx/8.
    // lane = (ty&1)*16 + tx, so tx-groups {0..7},{8..15} align with width-8
    // shuffle partitions.
    if (bn < 2) {
        const int head = bn * 2 + (tx >> 3);
        const int lcol = tx * 8;
        #pragma unroll
        for (int i = 0; i < 8; i++) {
            float pl = 0.f, pr = 0.f;
            #pragma unroll
            for (int j = 0; j < 8; j++) {
                pl += acc[i][j] * sal[lcol + j];
                pr += acc[i][j] * sar[lcol + j];
            }
            #pragma unroll
            for (int off = 4; off; off >>= 1) {
                pl += __shfl_down_sync(0xffffffffu, pl, off, 8);
                pr += __shfl_down_sync(0xffffffffu, pr, off, 8);
            }
            if ((tx & 7) == 0) {
                int grow = row0 + ty * 8 + i;
                if (grow < n) {
                    g_el[grow * HH + head] = pl;
                    g_er[grow * HH + head] = pr;
                }
            }
        }
    }
}

// ---------------- K4: edge logits + segment max + degree -------------------
// Warp per edge; 8-lane group g handles head g (g = lane/8, s = lane%8).
// Each lane dots 8 ef elements against v[g]; width-8 reduce (3 SHFL).
__global__ void __launch_bounds__(256) edge_logits(
        const float* __restrict__ ef, const int* __restrict__ src,
        const int* __restrict__ dst, int ne) {
    __shared__ float sv[HH][68];               // pad 64->68: 2-way max conflict
    int tid = threadIdx.x;
    if (tid < 256) sv[tid >> 6][tid & 63] = g_v[tid];
    __syncthreads();
    int e = blockIdx.x * 8 + (tid >> 5);
    if (e >= ne) return;
    int lane = tid & 31;
    int g = lane >> 3, s = lane & 7;
    const float* erow = ef + (size_t)e * F_EDGE + s * 8;
    float4 a0 = *(const float4*)erow;
    float4 a1 = *(const float4*)(erow + 4);
    const float* vv = &sv[g][s * 8];
    float p = a0.x * vv[0] + a0.y * vv[1] + a0.z * vv[2] + a0.w * vv[3]
            + a1.x * vv[4] + a1.y * vv[5] + a1.z * vv[6] + a1.w * vv[7];
    #pragma unroll
    for (int off = 4; off; off >>= 1)
        p += __shfl_down_sync(0xffffffffu, p, off, 8);
    if (s == 0) {                              // lanes 0,8,16,24 hold heads 0..3
        int sn = src[e], dn = dst[e];
        float ev = g_el[sn * HH + g] + g_er[dn * HH + g] + p;
        ev = (ev > 0.f) ? ev : NEG_SLOPE * ev;
        g_e[(size_t)e * HH + g] = ev;
        atomicMaxFloat(&g_m[dn * HH + g], ev);
    }
    if (lane == 1) atomicAdd(&g_deg[dst[e]], 1.0f);
}

// ---------------- K5+K6 fused: softmax numerators + aggregate --------------
// rst[dst] += exp(e - m[dst]) * feat[src]   (UNNORMALIZED)
// denom[dst] += exp(e - m[dst])             (single vector RED from lane 0)
// Normalization by denom is deferred to finalize (denom depends only on dst).
__global__ void __launch_bounds__(256) edge_softmax_aggregate(
        const int* __restrict__ src, const int* __restrict__ dst, int ne) {
    int tid = threadIdx.x;
    int e = blockIdx.x * 8 + (tid >> 5);
    if (e >= ne) return;
    int lane = tid & 31;
    int sn = src[e], dn = dst[e];
    float ex = 0.0f;
    if (lane < 4)
        ex = __expf(g_e[(size_t)e * HH + lane] - g_m[dn * HH + lane]);
    // gather heads 0..3 (lanes 0..3) into lane 0 -> one REDG.128
    float ex1 = __shfl_sync(0xffffffffu, ex, 1);
    float ex2 = __shfl_sync(0xffffffffu, ex, 2);
    float ex3 = __shfl_sync(0xffffffffu, ex, 3);
    if (lane == 0)
        atomicAdd((float4*)&g_denom[dn * HH], make_float4(ex, ex1, ex2, ex3));
    float ah = __shfl_sync(0xffffffffu, ex, lane >> 3);   // head = lane/8
    const float4* f = (const float4*)(g_feat + (size_t)sn * 256) + lane * 2;
    float4 v0 = f[0], v1 = f[1];
    float* p = g_rst + (size_t)dn * 256 + lane * 8;
    atomicAdd((float4*)p,       make_float4(v0.x * ah, v0.y * ah, v0.z * ah, v0.w * ah));
    atomicAdd((float4*)(p + 4), make_float4(v1.x * ah, v1.y * ah, v1.z * ah, v1.w * ah));
}

// ---------------- K7: out = res + rst / (denom * clip(deg,1)) --------------
__global__ void finalize(float* __restrict__ out, int n) {
    int i = blockIdx.x * blockDim.x + threadIdx.x;   // over n*64 float4s
    if (i >= n * 64) return;
    int node = i >> 6;
    int head = (i >> 4) & 3;                          // 16 float4s per head
    // denom >= 1 for any node with >=1 in-edge (max edge contributes exp(0)=1);
    // denom == 0 only when rst row is identically 0, so the clamp is inert.
    float inv = 1.0f / (fmaxf(g_deg[node], 1.0f)
                        * fmaxf(g_denom[node * HH + head], 1e-30f));
    float4 r = ((const float4*)g_rst)[i];
    float4 o = ((float4*)out)[i];
    o.x += r.x * inv; o.y += r.y * inv; o.z += r.z * inv; o.w += r.w * inv;
    ((float4*)out)[i] = o;
}

// ---------------- launch ---------------------------------------------------
extern "C" void kernel_launch(void* const* d_in, const int* in_sizes, int n_in,
                              void* d_out, int out_size) {
    const float* h    = (const float*)d_in[0];
    const float* ef   = (const float*)d_in[1];
    const int*   src  = (const int*)d_in[2];
    const int*   dst  = (const int*)d_in[3];
    const float* Wfc  = (const float*)d_in[4];
    const float* We   = (const float*)d_in[5];
    const float* Wres = (const float*)d_in[6];
    const float* al   = (const float*)d_in[7];
    const float* ar   = (const float*)d_in[8];
    const float* ae   = (const float*)d_in[9];
    float* out = (float*)d_out;

    int n  = in_sizes[0] / F_IN;   // 50000
    int ne = in_sizes[2];          // 800000

    void *prst, *pdenom, *pdeg, *pm;
    cudaGetSymbolAddress(&prst, g_rst);
    cudaGetSymbolAddress(&pdenom, g_denom);
    cudaGetSymbolAddress(&pdeg, g_deg);
    cudaGetSymbolAddress(&pm, g_m);
    cudaMemsetAsync(prst,   0,    sizeof(float) * (size_t)n * HD, 0);
    cudaMemsetAsync(pdenom, 0,    sizeof(float) * (size_t)n * HH, 0);
    cudaMemsetAsync(pdeg,   0,    sizeof(float) * (size_t)n, 0);
    cudaMemsetAsync(pm,     0xFF, sizeof(float) * (size_t)n * HH, 0);  // identity for atomicMaxFloat

    compute_ve<<<1, 256>>>(We, ae);

    dim3 gg((n + 127) / 128, 4);
    fused_gemm<<<gg, 256>>>(h, Wfc, Wres, al, ar, out, n);

    edge_logits<<<(ne + 7) / 8, 256>>>(ef, src, dst, ne);
    edge_softmax_aggregate<<<(ne + 7) / 8, 256>>>(src, dst, ne);
    finalize<<<(n * 64 + 255) / 256, 256>>>(out, n);
}

// round 14
// speedup vs baseline: 2.0281x; 2.0281x over previous
#include <cuda_runtime.h>
#include <math_constants.h>
#include <cstdint>

#define NN 50000
#define NE 800000
#define F_IN 256
#define F_EDGE 64
#define HH 4
#define DD 64
#define HD 256
#define NEG_SLOPE 0.2f

// ---------------- scratch (device globals; no allocation allowed) ----------
__device__ float g_feat[(size_t)NN * HD];    // h @ W_fc^T
__device__ float g_el[NN * HH];
__device__ float g_er[NN * HH];
__device__ float g_es[(size_t)NE * HH];      // logits in CSR (dst-grouped) order
__device__ int   g_srcs[NE];                 // src node ids in CSR order
__device__ float g_v[HH * F_EDGE];           // attn_e folded into W_edge
__device__ int   g_rowptr[NN + 1];           // CSR row offsets (by dst)
__device__ int   g_cursor[NN];               // hist, then scatter cursors
__device__ int   g_blocksum[256];            // scan partials (nb <= 256)

// ---------------- K0: fold attn_e into W_edge ------------------------------
__global__ void compute_ve(const float* __restrict__ W_edge,
                           const float* __restrict__ attn_e) {
    int tid = threadIdx.x;            // 256 threads: (h, c)
    int h = tid >> 6, c = tid & 63;
    float s = 0.0f;
    #pragma unroll 8
    for (int d = 0; d < DD; d++)
        s += attn_e[h * DD + d] * W_edge[(h * DD + d) * F_EDGE + c];
    g_v[tid] = s;
}

// ---------------- K2: fused GEMM  C[N,512] = h @ [W_fc | W_res]^T ----------
// 128x128 tile, BK=16, 256 threads, 8x8 per thread, double-buffered SMEM.
// blockIdx.y: 0,1 -> feat + fused el/er epilogue; 2,3 -> res into d_out.
__global__ void __launch_bounds__(256) fused_gemm(
        const float* __restrict__ A,      // h [n,256]
        const float* __restrict__ Wfc,    // [256,256]
        const float* __restrict__ Wres,   // [256,256]
        const float* __restrict__ attn_l, // [4,64] flat 256
        const float* __restrict__ attn_r, // [4,64] flat 256
        float* __restrict__ d_out, int n) {
    __shared__ float As[2][16][128];
    __shared__ float Bs[2][16][128];
    __shared__ float sal[128], sar[128];

    const int bm = blockIdx.x, bn = blockIdx.y;
    const float* W = (bn < 2) ? Wfc : Wres;
    const int wrow0 = (bn & 1) * 128;
    const int row0 = bm * 128;
    const int tid = threadIdx.x;
    const int tx = tid & 15, ty = tid >> 4;
    const int lr = tid >> 2;
    const int lc = (tid & 3) * 4;

    float acc[8][8] = {};

    auto load_tiles = [&](int k0, int buf) {
        #pragma unroll
        for (int r = 0; r < 2; r++) {
            int m = lr + r * 64;
            int grow = row0 + m;
            float4 v = make_float4(0.f, 0.f, 0.f, 0.f);
            if (grow < n)
                v = *(const float4*)(A + (size_t)grow * 256 + k0 + lc);
            As[buf][lc + 0][m] = v.x; As[buf][lc + 1][m] = v.y;
            As[buf][lc + 2][m] = v.z; As[buf][lc + 3][m] = v.w;
        }
        #pragma unroll
        for (int r = 0; r < 2; r++) {
            int nn2 = lr + r * 64;
            float4 v = *(const float4*)(W + (size_t)(wrow0 + nn2) * 256 + k0 + lc);
            Bs[buf][lc + 0][nn2] = v.x; Bs[buf][lc + 1][nn2] = v.y;
            Bs[buf][lc + 2][nn2] = v.z; Bs[buf][lc + 3][nn2] = v.w;
        }
    };

    if (bn < 2 && tid < 128) {
        sal[tid] = attn_l[bn * 128 + tid];
        sar[tid] = attn_r[bn * 128 + tid];
    }

    load_tiles(0, 0);
    __syncthreads();

    int buf = 0;
    for (int k0 = 0; k0 < 256; k0 += 16) {
        int nbuf = buf ^ 1;
        if (k0 + 16 < 256)
            load_tiles(k0 + 16, nbuf);
        #pragma unroll
        for (int k = 0; k < 16; k++) {
            float ra[8], rb[8];
            *(float4*)&ra[0] = *(const float4*)&As[buf][k][ty * 8];
            *(float4*)&ra[4] = *(const float4*)&As[buf][k][ty * 8 + 4];
            *(float4*)&rb[0] = *(const float4*)&Bs[buf][k][tx * 8];
            *(float4*)&rb[4] = *(const float4*)&Bs[buf][k][tx * 8 + 4];
            #pragma unroll
            for (int i = 0; i < 8; i++)
                #pragma unroll
                for (int j = 0; j < 8; j++)
                    acc[i][j] += ra[i] * rb[j];
        }
        __syncthreads();
        buf = nbuf;
    }

    float* dstbuf = (bn < 2) ? g_feat : d_out;
    const int colbase = (bn & 1) * 128 + tx * 8;
    #pragma unroll
    for (int i = 0; i < 8; i++) {
        int grow = row0 + ty * 8 + i;
        if (grow < n) {
            float* p = dstbuf + (size_t)grow * 256 + colbase;
            *(float4*)p       = make_float4(acc[i][0], acc[i][1], acc[i][2], acc[i][3]);
            *(float4*)(p + 4) = make_float4(acc[i][4], acc[i][5], acc[i][6], acc[i][7]);
        }
    }

    if (bn < 2) {   // fused el/er epilogue; head = bn*2 + tx/8, lane=(ty&1)*16+tx
        const int head = bn * 2 + (tx >> 3);
        const int lcol = tx * 8;
        #pragma unroll
        for (int i = 0; i < 8; i++) {
            float pl = 0.f, pr = 0.f;
            #pragma unroll
            for (int j = 0; j < 8; j++) {
                pl += acc[i][j] * sal[lcol + j];
                pr += acc[i][j] * sar[lcol + j];
            }
            #pragma unroll
            for (int off = 4; off; off >>= 1) {
                pl += __shfl_down_sync(0xffffffffu, pl, off, 8);
                pr += __shfl_down_sync(0xffffffffu, pr, off, 8);
            }
            if ((tx & 7) == 0) {
                int grow = row0 + ty * 8 + i;
                if (grow < n) {
                    g_el[grow * HH + head] = pl;
                    g_er[grow * HH + head] = pr;
                }
            }
        }
    }
}

// ---------------- CSR build: hist -> scan (cursor = rowptr) ----------------
__global__ void hist_kernel(const int* __restrict__ dst, int ne) {
    int e = blockIdx.x * blockDim.x + threadIdx.x;
    if (e < ne) atomicAdd(&g_cursor[dst[e]], 1);
}

__global__ void scan1(int n) {                 // block partial sums
    __shared__ int s[256];
    int idx = blockIdx.x * 256 + threadIdx.x;
    s[threadIdx.x] = (idx < n) ? g_cursor[idx] : 0;
    __syncthreads();
    for (int off = 128; off; off >>= 1) {
        if (threadIdx.x < off) s[threadIdx.x] += s[threadIdx.x + off];
        __syncthreads();
    }
    if (threadIdx.x == 0) g_blocksum[blockIdx.x] = s[0];
}

__global__ void scan2(int nb, int n) {         // exclusive scan of block sums
    __shared__ int s[256];
    int t = threadIdx.x;
    int v = (t < nb) ? g_blocksum[t] : 0;
    s[t] = v; __syncthreads();
    for (int off = 1; off < 256; off <<= 1) {
        int x = (t >= off) ? s[t - off] : 0;
        __syncthreads();
        s[t] += x;
        __syncthreads();
    }
    g_blocksum[t] = s[t] - v;                  // exclusive offset per block
    if (t == nb - 1) g_rowptr[n] = s[t];       // total = NE
}

__global__ void scan3(int n) {                 // final rowptr + cursor init
    __shared__ int s[256];
    int t = threadIdx.x;
    int idx = blockIdx.x * 256 + t;
    int v = (idx < n) ? g_cursor[idx] : 0;
    s[t] = v; __syncthreads();
    for (int off = 1; off < 256; off <<= 1) {
        int x = (t >= off) ? s[t - off] : 0;
        __syncthreads();
        s[t] += x;
        __syncthreads();
    }
    if (idx < n) {
        int val = g_blocksum[blockIdx.x] + s[t] - v;
        g_rowptr[idx] = val;
        g_cursor[idx] = val;
    }
}

// ---------------- K4: edge logits -> scatter to CSR slot -------------------
// Warp per edge; 8-lane group g handles head g. Lane 0 claims the CSR slot.
__global__ void __launch_bounds__(256) edge_logits_scatter(
        const float* __restrict__ ef, const int* __restrict__ src,
        const int* __restrict__ dst, int ne) {
    __shared__ float sv[HH][68];
    int tid = threadIdx.x;
    sv[tid >> 6][tid & 63] = g_v[tid];
    __syncthreads();
    int e = blockIdx.x * 8 + (tid >> 5);
    if (e >= ne) return;
    int lane = tid & 31;
    int g = lane >> 3, s = lane & 7;
    int sn = src[e], dn = dst[e];
    const float* erow = ef + (size_t)e * F_EDGE + s * 8;
    float4 a0 = *(const float4*)erow;
    float4 a1 = *(const float4*)(erow + 4);
    const float* vv = &sv[g][s * 8];
    float p = a0.x * vv[0] + a0.y * vv[1] + a0.z * vv[2] + a0.w * vv[3]
            + a1.x * vv[4] + a1.y * vv[5] + a1.z * vv[6] + a1.w * vv[7];
    #pragma unroll
    for (int off = 4; off; off >>= 1)
        p += __shfl_down_sync(0xffffffffu, p, off, 8);
    int pos = 0;
    if (lane == 0) pos = atomicAdd(&g_cursor[dn], 1);
    pos = __shfl_sync(0xffffffffu, pos, 0);
    if (s == 0) {                               // lanes 0,8,16,24: heads 0..3
        float ev = g_el[sn * HH + g] + g_er[dn * HH + g] + p;
        ev = (ev > 0.f) ? ev : NEG_SLOPE * ev;
        g_es[(size_t)pos * HH + g] = ev;
    }
    if (lane == 1) g_srcs[pos] = sn;
}

// ---------------- K6: per-node softmax + aggregate + residual add ----------
// Warp per dst node; coalesced CSR streams; 4-edge unroll; ZERO atomics.
__global__ void __launch_bounds__(256) node_aggregate(
        float* __restrict__ out, int n) {
    int tid = threadIdx.x;
    int node = blockIdx.x * 8 + (tid >> 5);
    if (node >= n) return;
    int lane = tid & 31;
    int beg = g_rowptr[node], end = g_rowptr[node + 1];
    int deg = end - beg;
    if (deg == 0) return;                       // out already holds res

    // pass 1: per-head maxima (coalesced float4 stream)
    float m0 = -CUDART_INF_F, m1 = m0, m2 = m0, m3 = m0;
    for (int j = beg + lane; j < end; j += 32) {
        float4 ev = ((const float4*)g_es)[j];
        m0 = fmaxf(m0, ev.x); m1 = fmaxf(m1, ev.y);
        m2 = fmaxf(m2, ev.z); m3 = fmaxf(m3, ev.w);
    }
    #pragma unroll
    for (int off = 16; off; off >>= 1) {
        m0 = fmaxf(m0, __shfl_xor_sync(0xffffffffu, m0, off));
        m1 = fmaxf(m1, __shfl_xor_sync(0xffffffffu, m1, off));
        m2 = fmaxf(m2, __shfl_xor_sync(0xffffffffu, m2, off));
        m3 = fmaxf(m3, __shfl_xor_sync(0xffffffffu, m3, off));
    }
    float mym = (lane == 0) ? m0 : (lane == 1) ? m1 : (lane == 2) ? m2 : m3;

    // pass 2: accumulate (4-edge unroll for load-latency overlap)
    float acc[8] = {};
    float denom = 0.f;                          // valid on lanes 0..3
    const int hsel = lane >> 3;                 // head source lane (0..3)
    int j = beg;
    for (; j + 3 < end; j += 4) {
        int sn0 = g_srcs[j],     sn1 = g_srcs[j + 1];
        int sn2 = g_srcs[j + 2], sn3 = g_srcs[j + 3];
        float ex0 = 0.f, ex1 = 0.f, ex2 = 0.f, ex3 = 0.f;
        if (lane < 4) {
            ex0 = __expf(g_es[(size_t)j * HH + lane] - mym);
            ex1 = __expf(g_es[(size_t)(j + 1) * HH + lane] - mym);
            ex2 = __expf(g_es[(size_t)(j + 2) * HH + lane] - mym);
            ex3 = __expf(g_es[(size_t)(j + 3) * HH + lane] - mym);
            denom += (ex0 + ex1) + (ex2 + ex3);
        }
        float ah0 = __shfl_sync(0xffffffffu, ex0, hsel);
        float ah1 = __shfl_sync(0xffffffffu, ex1, hsel);
        float ah2 = __shfl_sync(0xffffffffu, ex2, hsel);
        float ah3 = __shfl_sync(0xffffffffu, ex3, hsel);
        const float4* f0 = (const float4*)(g_feat + (size_t)sn0 * 256) + lane * 2;
        const float4* f1 = (const float4*)(g_feat + (size_t)sn1 * 256) + lane * 2;
        const float4* f2 = (const float4*)(g_feat + (size_t)sn2 * 256) + lane * 2;
        const float4* f3 = (const float4*)(g_feat + (size_t)sn3 * 256) + lane * 2;
        float4 a0 = f0[0], b0 = f0[1];
        float4 a1 = f1[0], b1 = f1[1];
        float4 a2 = f2[0], b2 = f2[1];
        float4 a3 = f3[0], b3 = f3[1];
        acc[0] += ah0 * a0.x + ah1 * a1.x + ah2 * a2.x + ah3 * a3.x;
        acc[1] += ah0 * a0.y + ah1 * a1.y + ah2 * a2.y + ah3 * a3.y;
        acc[2] += ah0 * a0.z + ah1 * a1.z + ah2 * a2.z + ah3 * a3.z;
        acc[3] += ah0 * a0.w + ah1 * a1.w + ah2 * a2.w + ah3 * a3.w;
        acc[4] += ah0 * b0.x + ah1 * b1.x + ah2 * b2.x + ah3 * b3.x;
        acc[5] += ah0 * b0.y + ah1 * b1.y + ah2 * b2.y + ah3 * b3.y;
        acc[6] += ah0 * b0.z + ah1 * b1.z + ah2 * b2.z + ah3 * b3.z;
        acc[7] += ah0 * b0.w + ah1 * b1.w + ah2 * b2.w + ah3 * b3.w;
    }
    for (; j < end; j++) {
        int sn = g_srcs[j];
        float ex = 0.f;
        if (lane < 4) {
            ex = __expf(g_es[(size_t)j * HH + lane] - mym);
            denom += ex;
        }
        float ah = __shfl_sync(0xffffffffu, ex, hsel);
        const float4* f = (const float4*)(g_feat + (size_t)sn * 256) + lane * 2;
        float4 a = f[0], b = f[1];
        acc[0] += ah * a.x; acc[1] += ah * a.y;
        acc[2] += ah * a.z; acc[3] += ah * a.w;
        acc[4] += ah * b.x; acc[5] += ah * b.y;
        acc[6] += ah * b.z; acc[7] += ah * b.w;
    }
    float dh = __shfl_sync(0xffffffffu, denom, hsel);
    float inv = 1.0f / (dh * (float)deg);
    float* p = out + (size_t)node * 256 + lane * 8;
    float4 o0 = *(float4*)p, o1 = *(float4*)(p + 4);
    o0.x += acc[0] * inv; o0.y += acc[1] * inv;
    o0.z += acc[2] * inv; o0.w += acc[3] * inv;
    o1.x += acc[4] * inv; o1.y += acc[5] * inv;
    o1.z += acc[6] * inv; o1.w += acc[7] * inv;
    *(float4*)p = o0; *(float4*)(p + 4) = o1;
}

// ---------------- launch ---------------------------------------------------
extern "C" void kernel_launch(void* const* d_in, const int* in_sizes, int n_in,
                              void* d_out, int out_size) {
    const float* h    = (const float*)d_in[0];
    const float* ef   = (const float*)d_in[1];
    const int*   src  = (const int*)d_in[2];
    const int*   dst  = (const int*)d_in[3];
    const float* Wfc  = (const float*)d_in[4];
    const float* We   = (const float*)d_in[5];
    const float* Wres = (const float*)d_in[6];
    const float* al   = (const float*)d_in[7];
    const float* ar   = (const float*)d_in[8];
    const float* ae   = (const float*)d_in[9];
    float* out = (float*)d_out;

    int n  = in_sizes[0] / F_IN;   // 50000
    int ne = in_sizes[2];          // 800000
    int nb = (n + 255) / 256;      // scan blocks (<=256)

    // Lazy one-time stream/event creation (host-side, no device allocation).
    static cudaStream_t s2 = nullptr;
    static cudaEvent_t ev_fork = nullptr, ev_join = nullptr;
    if (s2 == nullptr) {
        cudaStreamCreateWithFlags(&s2, cudaStreamNonBlocking);
        cudaEventCreateWithFlags(&ev_fork, cudaEventDisableTiming);
        cudaEventCreateWithFlags(&ev_join, cudaEventDisableTiming);
    }

    void* pcur;
    cudaGetSymbolAddress(&pcur, g_cursor);

    // Fork: side stream builds CSR while stream 0 runs compute_ve + GEMM.
    cudaEventRecord(ev_fork, 0);
    cudaStreamWaitEvent(s2, ev_fork, 0);

    // side chain (s2): CSR over dst
    cudaMemsetAsync(pcur, 0, sizeof(int) * (size_t)n, s2);
    hist_kernel<<<(ne + 255) / 256, 256, 0, s2>>>(dst, ne);
    scan1<<<nb, 256, 0, s2>>>(n);
    scan2<<<1, 256, 0, s2>>>(nb, n);
    scan3<<<nb, 256, 0, s2>>>(n);
    cudaEventRecord(ev_join, s2);

    // main chain (stream 0)
    compute_ve<<<1, 256>>>(We, ae);
    dim3 gg((n + 127) / 128, 4);
    fused_gemm<<<gg, 256>>>(h, Wfc, Wres, al, ar, out, n);

    // Join: logits scatter needs GEMM outputs AND the CSR cursors.
    cudaStreamWaitEvent(0, ev_join, 0);
    edge_logits_scatter<<<(ne + 7) / 8, 256>>>(ef, src, dst, ne);

    node_aggregate<<<(n + 7) / 8, 256>>>(out, n);
}

// round 15
// speedup vs baseline: 2.4300x; 1.1982x over previous
#include <cuda_runtime.h>
#include <math_constants.h>
#include <cstdint>

#define NN 50000
#define NE 800000
#define F_IN 256
#define F_EDGE 64
#define HH 4
#define DD 64
#define HD 256
#define NEG_SLOPE 0.2f

// ---------------- scratch (device globals; no allocation allowed) ----------
__device__ float g_feat[(size_t)NN * HD];    // h @ W_fc^T
__device__ float g_el[NN * HH];
__device__ float g_er[NN * HH];
__device__ float g_es[(size_t)NE * HH];      // logits in CSR (dst-grouped) order
__device__ int   g_srcs[NE];                 // src node ids in CSR order
__device__ float g_v[HH * F_EDGE];           // attn_e folded into W_edge
__device__ int   g_rowptr[NN + 1];           // CSR row offsets (by dst)
__device__ int   g_cursor[NN];               // hist, then scatter cursors
__device__ int   g_blocksum[256];            // scan partials (nb <= 256)

__device__ __forceinline__ uint32_t f2tf32(float f) {
    uint32_t u;
    asm("cvt.rna.tf32.f32 %0, %1;" : "=r"(u) : "f"(f));
    return u;
}

// ---------------- K0: fold attn_e into W_edge ------------------------------
__global__ void compute_ve(const float* __restrict__ W_edge,
                           const float* __restrict__ attn_e) {
    int tid = threadIdx.x;            // 256 threads: (h, c)
    int h = tid >> 6, c = tid & 63;
    float s = 0.0f;
    #pragma unroll 8
    for (int d = 0; d < DD; d++)
        s += attn_e[h * DD + d] * W_edge[(h * DD + d) * F_EDGE + c];
    g_v[tid] = s;
}

// ---------------- K2: TF32 tensor-core GEMM  C[N,512] = h @ [Wfc|Wres]^T ---
// 128x128 tile, BK=32 double-buffered, 8 warps (2M x 4N), m16n8k8 atoms.
// blockIdx.y: 0,1 -> feat (cols 0..255); 2,3 -> res into d_out.
#define BK 32
#define LDS_PAD 33
__global__ void __launch_bounds__(256) fused_gemm_tc(
        const float* __restrict__ A,      // h [n,256]
        const float* __restrict__ Wfc,    // [256,256]
        const float* __restrict__ Wres,   // [256,256]
        float* __restrict__ d_out, int n) {
    __shared__ uint32_t As[2][128][LDS_PAD];   // [row][k], tf32 bits
    __shared__ uint32_t Bs[2][128][LDS_PAD];   // [outcol][k], tf32 bits

    const int bm = blockIdx.x, bn = blockIdx.y;
    const float* W = (bn < 2) ? Wfc : Wres;
    const int wrow0 = (bn & 1) * 128;          // W row offset (= output col base)
    const int row0 = bm * 128;
    const int tid = threadIdx.x;
    const int lane = tid & 31;
    const int warp = tid >> 5;                 // 0..7
    const int warpM = warp & 1;                // 2 x 64 rows
    const int warpN = warp >> 1;               // 4 x 32 cols
    const int lrow = tid >> 1;                 // 0..127 (tile row / outcol)
    const int lk   = (tid & 1) * 16;           // 0 or 16

    float acc[4][4][4] = {};                   // [mi][ni][reg]

    auto load_tiles = [&](int k0, int buf) {
        int grow = row0 + lrow;
        if (grow < n) {
            const float* pa = A + (size_t)grow * 256 + k0 + lk;
            #pragma unroll
            for (int i = 0; i < 16; i += 4) {
                float4 v = *(const float4*)(pa + i);
                As[buf][lrow][lk + i + 0] = f2tf32(v.x);
                As[buf][lrow][lk + i + 1] = f2tf32(v.y);
                As[buf][lrow][lk + i + 2] = f2tf32(v.z);
                As[buf][lrow][lk + i + 3] = f2tf32(v.w);
            }
        } else {
            #pragma unroll
            for (int i = 0; i < 16; i++) As[buf][lrow][lk + i] = 0u;
        }
        const float* pb = W + (size_t)(wrow0 + lrow) * 256 + k0 + lk;
        #pragma unroll
        for (int i = 0; i < 16; i += 4) {
            float4 v = *(const float4*)(pb + i);
            Bs[buf][lrow][lk + i + 0] = f2tf32(v.x);
            Bs[buf][lrow][lk + i + 1] = f2tf32(v.y);
            Bs[buf][lrow][lk + i + 2] = f2tf32(v.z);
            Bs[buf][lrow][lk + i + 3] = f2tf32(v.w);
        }
    };

    load_tiles(0, 0);
    __syncthreads();

    const int lg = lane >> 2;                  // 0..7 group
    const int lq = lane & 3;                   // 0..3 in group
    int buf = 0;
    for (int k0 = 0; k0 < 256; k0 += BK) {
        int nbuf = buf ^ 1;
        if (k0 + BK < 256)
            load_tiles(k0 + BK, nbuf);
        #pragma unroll
        for (int kk = 0; kk < BK / 8; kk++) {
            const int kb = kk * 8;
            uint32_t afr[4][4];
            #pragma unroll
            for (int mi = 0; mi < 4; mi++) {
                int r0 = warpM * 64 + mi * 16 + lg;
                afr[mi][0] = As[buf][r0][kb + lq];
                afr[mi][1] = As[buf][r0 + 8][kb + lq];
                afr[mi][2] = As[buf][r0][kb + lq + 4];
                afr[mi][3] = As[buf][r0 + 8][kb + lq + 4];
            }
            uint32_t bfr[4][2];
            #pragma unroll
            for (int ni = 0; ni < 4; ni++) {
                int c0 = warpN * 32 + ni * 8 + lg;
                bfr[ni][0] = Bs[buf][c0][kb + lq];
                bfr[ni][1] = Bs[buf][c0][kb + lq + 4];
            }
            #pragma unroll
            for (int mi = 0; mi < 4; mi++)
                #pragma unroll
                for (int ni = 0; ni < 4; ni++) {
                    float* c = acc[mi][ni];
                    asm volatile(
                        "mma.sync.aligned.m16n8k8.row.col.f32.tf32.tf32.f32 "
                        "{%0,%1,%2,%3}, {%4,%5,%6,%7}, {%8,%9}, {%0,%1,%2,%3};"
                        : "+f"(c[0]), "+f"(c[1]), "+f"(c[2]), "+f"(c[3])
                        : "r"(afr[mi][0]), "r"(afr[mi][1]),
                          "r"(afr[mi][2]), "r"(afr[mi][3]),
                          "r"(bfr[ni][0]), "r"(bfr[ni][1]));
                }
        }
        __syncthreads();
        buf = nbuf;
    }

    float* dstbuf = (bn < 2) ? g_feat : d_out;
    #pragma unroll
    for (int mi = 0; mi < 4; mi++) {
        int row = row0 + warpM * 64 + mi * 16 + lg;
        #pragma unroll
        for (int ni = 0; ni < 4; ni++) {
            int col = wrow0 + warpN * 32 + ni * 8 + 2 * lq;
            if (row < n)
                *(float2*)(dstbuf + (size_t)row * 256 + col)
                    = make_float2(acc[mi][ni][0], acc[mi][ni][1]);
            if (row + 8 < n)
                *(float2*)(dstbuf + (size_t)(row + 8) * 256 + col)
                    = make_float2(acc[mi][ni][2], acc[mi][ni][3]);
        }
    }
}

// ---------------- K3: el / er per node (warp per node) ---------------------
__global__ void __launch_bounds__(256) node_attn(
        const float* __restrict__ attn_l, const float* __restrict__ attn_r, int n) {
    __shared__ float sl[256], sr[256];
    int tid = threadIdx.x;
    sl[tid] = attn_l[tid];
    sr[tid] = attn_r[tid];
    __syncthreads();
    int node = blockIdx.x * 8 + (tid >> 5);
    if (node >= n) return;
    int lane = tid & 31;
    const float* f = g_feat + (size_t)node * 256;
    int base = lane * 8;
    float4 f0 = *(const float4*)(f + base);
    float4 f1 = *(const float4*)(f + base + 4);
    float fv[8] = {f0.x, f0.y, f0.z, f0.w, f1.x, f1.y, f1.z, f1.w};
    float pl = 0.f, pr = 0.f;
    #pragma unroll
    for (int i = 0; i < 8; i++) {
        pl += fv[i] * sl[base + i];
        pr += fv[i] * sr[base + i];
    }
    #pragma unroll
    for (int off = 4; off; off >>= 1) {
        pl += __shfl_down_sync(0xffffffffu, pl, off, 8);
        pr += __shfl_down_sync(0xffffffffu, pr, off, 8);
    }
    if ((lane & 7) == 0) {
        int h = lane >> 3;
        g_el[node * HH + h] = pl;
        g_er[node * HH + h] = pr;
    }
}

// ---------------- CSR build: hist -> scan (cursor = rowptr) ----------------
__global__ void hist_kernel(const int* __restrict__ dst, int ne) {
    int e = blockIdx.x * blockDim.x + threadIdx.x;
    if (e < ne) atomicAdd(&g_cursor[dst[e]], 1);
}

__global__ void scan1(int n) {                 // block partial sums
    __shared__ int s[256];
    int idx = blockIdx.x * 256 + threadIdx.x;
    s[threadIdx.x] = (idx < n) ? g_cursor[idx] : 0;
    __syncthreads();
    for (int off = 128; off; off >>= 1) {
        if (threadIdx.x < off) s[threadIdx.x] += s[threadIdx.x + off];
        __syncthreads();
    }
    if (threadIdx.x == 0) g_blocksum[blockIdx.x] = s[0];
}

__global__ void scan2(int nb, int n) {         // exclusive scan of block sums
    __shared__ int s[256];
    int t = threadIdx.x;
    int v = (t < nb) ? g_blocksum[t] : 0;
    s[t] = v; __syncthreads();
    for (int off = 1; off < 256; off <<= 1) {
        int x = (t >= off) ? s[t - off] : 0;
        __syncthreads();
        s[t] += x;
        __syncthreads();
    }
    g_blocksum[t] = s[t] - v;                  // exclusive offset per block
    if (t == nb - 1) g_rowptr[n] = s[t];       // total = NE
}

__global__ void scan3(int n) {                 // final rowptr + cursor init
    __shared__ int s[256];
    int t = threadIdx.x;
    int idx = blockIdx.x * 256 + t;
    int v = (idx < n) ? g_cursor[idx] : 0;
    s[t] = v; __syncthreads();
    for (int off = 1; off < 256; off <<= 1) {
        int x = (t >= off) ? s[t - off] : 0;
        __syncthreads();
        s[t] += x;
        __syncthreads();
    }
    if (idx < n) {
        int val = g_blocksum[blockIdx.x] + s[t] - v;
        g_rowptr[idx] = val;
        g_cursor[idx] = val;
    }
}

// ---------------- K4: edge logits -> scatter to CSR slot -------------------
// Warp per edge; 8-lane group g handles head g. Lane 0 claims the CSR slot.
__global__ void __launch_bounds__(256) edge_logits_scatter(
        const float* __restrict__ ef, const int* __restrict__ src,
        const int* __restrict__ dst, int ne) {
    __shared__ float sv[HH][68];
    int tid = threadIdx.x;
    sv[tid >> 6][tid & 63] = g_v[tid];
    __syncthreads();
    int e = blockIdx.x * 8 + (tid >> 5);
    if (e >= ne) return;
    int lane = tid & 31;
    int g = lane >> 3, s = lane & 7;
    int sn = src[e], dn = dst[e];
    const float* erow = ef + (size_t)e * F_EDGE + s * 8;
    float4 a0 = *(const float4*)erow;
    float4 a1 = *(const float4*)(erow + 4);
    const float* vv = &sv[g][s * 8];
    float p = a0.x * vv[0] + a0.y * vv[1] + a0.z * vv[2] + a0.w * vv[3]
            + a1.x * vv[4] + a1.y * vv[5] + a1.z * vv[6] + a1.w * vv[7];
    #pragma unroll
    for (int off = 4; off; off >>= 1)
        p += __shfl_down_sync(0xffffffffu, p, off, 8);
    int pos = 0;
    if (lane == 0) pos = atomicAdd(&g_cursor[dn], 1);
    pos = __shfl_sync(0xffffffffu, pos, 0);
    if (s == 0) {                               // lanes 0,8,16,24: heads 0..3
        float ev = g_el[sn * HH + g] + g_er[dn * HH + g] + p;
        ev = (ev > 0.f) ? ev : NEG_SLOPE * ev;
        g_es[(size_t)pos * HH + g] = ev;
    }
    if (lane == 1) g_srcs[pos] = sn;
}

// ---------------- K6: per-node softmax + aggregate + residual add ----------
// Warp per dst node; coalesced CSR streams; 4-edge unroll; ZERO atomics.
__global__ void __launch_bounds__(256) node_aggregate(
        float* __restrict__ out, int n) {
    int tid = threadIdx.x;
    int node = blockIdx.x * 8 + (tid >> 5);
    if (node >= n) return;
    int lane = tid & 31;
    int beg = g_rowptr[node], end = g_rowptr[node + 1];
    int deg = end - beg;
    if (deg == 0) return;                       // out already holds res

    // pass 1: per-head maxima (coalesced float4 stream)
    float m0 = -CUDART_INF_F, m1 = m0, m2 = m0, m3 = m0;
    for (int j = beg + lane; j < end; j += 32) {
        float4 ev = ((const float4*)g_es)[j];
        m0 = fmaxf(m0, ev.x); m1 = fmaxf(m1, ev.y);
        m2 = fmaxf(m2, ev.z); m3 = fmaxf(m3, ev.w);
    }
    #pragma unroll
    for (int off = 16; off; off >>= 1) {
        m0 = fmaxf(m0, __shfl_xor_sync(0xffffffffu, m0, off));
        m1 = fmaxf(m1, __shfl_xor_sync(0xffffffffu, m1, off));
        m2 = fmaxf(m2, __shfl_xor_sync(0xffffffffu, m2, off));
        m3 = fmaxf(m3, __shfl_xor_sync(0xffffffffu, m3, off));
    }
    float mym = (lane == 0) ? m0 : (lane == 1) ? m1 : (lane == 2) ? m2 : m3;

    // pass 2: accumulate (4-edge unroll for load-latency overlap)
    float acc[8] = {};
    float denom = 0.f;                          // valid on lanes 0..3
    const int hsel = lane >> 3;                 // head source lane (0..3)
    int j = beg;
    for (; j + 3 < end; j += 4) {
        int sn0 = g_srcs[j],     sn1 = g_srcs[j + 1];
        int sn2 = g_srcs[j + 2], sn3 = g_srcs[j + 3];
        float ex0 = 0.f, ex1 = 0.f, ex2 = 0.f, ex3 = 0.f;
        if (lane < 4) {
            ex0 = __expf(g_es[(size_t)j * HH + lane] - mym);
            ex1 = __expf(g_es[(size_t)(j + 1) * HH + lane] - mym);
            ex2 = __expf(g_es[(size_t)(j + 2) * HH + lane] - mym);
            ex3 = __expf(g_es[(size_t)(j + 3) * HH + lane] - mym);
            denom += (ex0 + ex1) + (ex2 + ex3);
        }
        float ah0 = __shfl_sync(0xffffffffu, ex0, hsel);
        float ah1 = __shfl_sync(0xffffffffu, ex1, hsel);
        float ah2 = __shfl_sync(0xffffffffu, ex2, hsel);
        float ah3 = __shfl_sync(0xffffffffu, ex3, hsel);
        const float4* f0 = (const float4*)(g_feat + (size_t)sn0 * 256) + lane * 2;
        const float4* f1 = (const float4*)(g_feat + (size_t)sn1 * 256) + lane * 2;
        const float4* f2 = (const float4*)(g_feat + (size_t)sn2 * 256) + lane * 2;
        const float4* f3 = (const float4*)(g_feat + (size_t)sn3 * 256) + lane * 2;
        float4 a0 = f0[0], b0 = f0[1];
        float4 a1 = f1[0], b1 = f1[1];
        float4 a2 = f2[0], b2 = f2[1];
        float4 a3 = f3[0], b3 = f3[1];
        acc[0] += ah0 * a0.x + ah1 * a1.x + ah2 * a2.x + ah3 * a3.x;
        acc[1] += ah0 * a0.y + ah1 * a1.y + ah2 * a2.y + ah3 * a3.y;
        acc[2] += ah0 * a0.z + ah1 * a1.z + ah2 * a2.z + ah3 * a3.z;
        acc[3] += ah0 * a0.w + ah1 * a1.w + ah2 * a2.w + ah3 * a3.w;
        acc[4] += ah0 * b0.x + ah1 * b1.x + ah2 * b2.x + ah3 * b3.x;
        acc[5] += ah0 * b0.y + ah1 * b1.y + ah2 * b2.y + ah3 * b3.y;
        acc[6] += ah0 * b0.z + ah1 * b1.z + ah2 * b2.z + ah3 * b3.z;
        acc[7] += ah0 * b0.w + ah1 * b1.w + ah2 * b2.w + ah3 * b3.w;
    }
    for (; j < end; j++) {
        int sn = g_srcs[j];
        float ex = 0.f;
        if (lane < 4) {
            ex = __expf(g_es[(size_t)j * HH + lane] - mym);
            denom += ex;
        }
        float ah = __shfl_sync(0xffffffffu, ex, hsel);
        const float4* f = (const float4*)(g_feat + (size_t)sn * 256) + lane * 2;
        float4 a = f[0], b = f[1];
        acc[0] += ah * a.x; acc[1] += ah * a.y;
        acc[2] += ah * a.z; acc[3] += ah * a.w;
        acc[4] += ah * b.x; acc[5] += ah * b.y;
        acc[6] += ah * b.z; acc[7] += ah * b.w;
    }
    float dh = __shfl_sync(0xffffffffu, denom, hsel);
    float inv = 1.0f / (dh * (float)deg);
    float* p = out + (size_t)node * 256 + lane * 8;
    float4 o0 = *(float4*)p, o1 = *(float4*)(p + 4);
    o0.x += acc[0] * inv; o0.y += acc[1] * inv;
    o0.z += acc[2] * inv; o0.w += acc[3] * inv;
    o1.x += acc[4] * inv; o1.y += acc[5] * inv;
    o1.z += acc[6] * inv; o1.w += acc[7] * inv;
    *(float4*)p = o0; *(float4*)(p + 4) = o1;
}

// ---------------- launch ---------------------------------------------------
extern "C" void kernel_launch(void* const* d_in, const int* in_sizes, int n_in,
                              void* d_out, int out_size) {
    const float* h    = (const float*)d_in[0];
    const float* ef   = (const float*)d_in[1];
    const int*   src  = (const int*)d_in[2];
    const int*   dst  = (const int*)d_in[3];
    const float* Wfc  = (const float*)d_in[4];
    const float* We   = (const float*)d_in[5];
    const float* Wres = (const float*)d_in[6];
    const float* al   = (const float*)d_in[7];
    const float* ar   = (const float*)d_in[8];
    const float* ae   = (const float*)d_in[9];
    float* out = (float*)d_out;

    int n  = in_sizes[0] / F_IN;   // 50000
    int ne = in_sizes[2];          // 800000
    int nb = (n + 255) / 256;      // scan blocks (<=256)

    // Lazy one-time stream/event creation (host-side, no device allocation).
    static cudaStream_t s2 = nullptr;
    static cudaEvent_t ev_fork = nullptr, ev_join = nullptr;
    if (s2 == nullptr) {
        cudaStreamCreateWithFlags(&s2, cudaStreamNonBlocking);
        cudaEventCreateWithFlags(&ev_fork, cudaEventDisableTiming);
        cudaEventCreateWithFlags(&ev_join, cudaEventDisableTiming);
    }

    void* pcur;
    cudaGetSymbolAddress(&pcur, g_cursor);

    // Fork: side stream builds CSR while stream 0 runs compute_ve + GEMM.
    cudaEventRecord(ev_fork, 0);
    cudaStreamWaitEvent(s2, ev_fork, 0);

    // side chain (s2): CSR over dst
    cudaMemsetAsync(pcur, 0, sizeof(int) * (size_t)n, s2);
    hist_kernel<<<(ne + 255) / 256, 256, 0, s2>>>(dst, ne);
    scan1<<<nb, 256, 0, s2>>>(n);
    scan2<<<1, 256, 0, s2>>>(nb, n);
    scan3<<<nb, 256, 0, s2>>>(n);
    cudaEventRecord(ev_join, s2);

    // main chain (stream 0)
    compute_ve<<<1, 256>>>(We, ae);
    dim3 gg((n + 127) / 128, 4);
    fused_gemm_tc<<<gg, 256>>>(h, Wfc, Wres, out, n);
    node_attn<<<(n + 7) / 8, 256>>>(al, ar, n);

    // Join: logits scatter needs el/er + g_v AND the CSR cursors.
    cudaStreamWaitEvent(0, ev_join, 0);
    edge_logits_scatter<<<(ne + 7) / 8, 256>>>(ef, src, dst, ne);

    node_aggregate<<<(n + 7) / 8, 256>>>(out, n);
}

// round 17
// speedup vs baseline: 2.5489x; 1.0489x over previous
#include <cuda_runtime.h>
#include <math_constants.h>
#include <cstdint>

#define NN 50000
#define NE 800000
#define F_IN 256
#define F_EDGE 64
#define HH 4
#define DD 64
#define HD 256
#define NEG_SLOPE 0.2f

// ---------------- scratch (device globals; no allocation allowed) ----------
__device__ float g_feat[(size_t)NN * HD];    // h @ W_fc^T
__device__ float g_el[NN * HH];
__device__ float g_er[NN * HH];
__device__ float g_es[(size_t)NE * HH];      // ee, then full logits (CSR order)
__device__ int   g_srcs[NE];                 // src node ids in CSR order
__device__ float g_v[HH * F_EDGE];           // attn_e folded into W_edge
__device__ int   g_rowptr[NN + 1];           // CSR row offsets (by dst)
__device__ int   g_cursor[NN];               // hist, then scatter cursors
__device__ int   g_blocksum[256];            // scan partials (nb <= 256)

__device__ __forceinline__ uint32_t f2tf32(float f) {
    uint32_t u;
    asm("cvt.rna.tf32.f32 %0, %1;" : "=r"(u) : "f"(f));
    return u;
}

// ---------------- K0: fold attn_e into W_edge ------------------------------
__global__ void compute_ve(const float* __restrict__ W_edge,
                           const float* __restrict__ attn_e) {
    int tid = threadIdx.x;            // 256 threads: (h, c)
    int h = tid >> 6, c = tid & 63;
    float s = 0.0f;
    #pragma unroll 8
    for (int d = 0; d < DD; d++)
        s += attn_e[h * DD + d] * W_edge[(h * DD + d) * F_EDGE + c];
    g_v[tid] = s;
}

// ---------------- K2: TF32 tensor-core GEMM  C[N,512] = h @ [Wfc|Wres]^T ---
// 128x128 tile, BK=32 double-buffered, 8 warps (2M x 4N), m16n8k8 atoms.
// bn = blockIdx.y + bn_base: 0,1 -> feat (cols 0..255); 2,3 -> res to d_out.
#define BK 32
#define LDS_PAD 33
__global__ void __launch_bounds__(256) fused_gemm_tc(
        const float* __restrict__ A,      // h [n,256]
        const float* __restrict__ Wfc,    // [256,256]
        const float* __restrict__ Wres,   // [256,256]
        float* __restrict__ d_out, int n, int bn_base) {
    __shared__ uint32_t As[2][128][LDS_PAD];   // [row][k], tf32 bits
    __shared__ uint32_t Bs[2][128][LDS_PAD];   // [outcol][k], tf32 bits

    const int bm = blockIdx.x, bn = blockIdx.y + bn_base;
    const float* W = (bn < 2) ? Wfc : Wres;
    const int wrow0 = (bn & 1) * 128;          // W row offset (= output col base)
    const int row0 = bm * 128;
    const int tid = threadIdx.x;
    const int lane = tid & 31;
    const int warp = tid >> 5;                 // 0..7
    const int warpM = warp & 1;                // 2 x 64 rows
    const int warpN = warp >> 1;               // 4 x 32 cols
    const int lrow = tid >> 1;                 // 0..127 (tile row / outcol)
    const int lk   = (tid & 1) * 16;           // 0 or 16

    float acc[4][4][4] = {};                   // [mi][ni][reg]

    auto load_tiles = [&](int k0, int buf) {
        int grow = row0 + lrow;
        if (grow < n) {
            const float* pa = A + (size_t)grow * 256 + k0 + lk;
            #pragma unroll
            for (int i = 0; i < 16; i += 4) {
                float4 v = *(const float4*)(pa + i);
                As[buf][lrow][lk + i + 0] = f2tf32(v.x);
                As[buf][lrow][lk + i + 1] = f2tf32(v.y);
                As[buf][lrow][lk + i + 2] = f2tf32(v.z);
                As[buf][lrow][lk + i + 3] = f2tf32(v.w);
            }
        } else {
            #pragma unroll
            for (int i = 0; i < 16; i++) As[buf][lrow][lk + i] = 0u;
        }
        const float* pb = W + (size_t)(wrow0 + lrow) * 256 + k0 + lk;
        #pragma unroll
        for (int i = 0; i < 16; i += 4) {
            float4 v = *(const float4*)(pb + i);
            Bs[buf][lrow][lk + i + 0] = f2tf32(v.x);
            Bs[buf][lrow][lk + i + 1] = f2tf32(v.y);
            Bs[buf][lrow][lk + i + 2] = f2tf32(v.z);
            Bs[buf][lrow][lk + i + 3] = f2tf32(v.w);
        }
    };

    load_tiles(0, 0);
    __syncthreads();

    const int lg = lane >> 2;                  // 0..7 group
    const int lq = lane & 3;                   // 0..3 in group
    int buf = 0;
    for (int k0 = 0; k0 < 256; k0 += BK) {
        int nbuf = buf ^ 1;
        if (k0 + BK < 256)
            load_tiles(k0 + BK, nbuf);
        #pragma unroll
        for (int kk = 0; kk < BK / 8; kk++) {
            const int kb = kk * 8;
            uint32_t afr[4][4];
            #pragma unroll
            for (int mi = 0; mi < 4; mi++) {
                int r0 = warpM * 64 + mi * 16 + lg;
                afr[mi][0] = As[buf][r0][kb + lq];
                afr[mi][1] = As[buf][r0 + 8][kb + lq];
                afr[mi][2] = As[buf][r0][kb + lq + 4];
                afr[mi][3] = As[buf][r0 + 8][kb + lq + 4];
            }
            uint32_t bfr[4][2];
            #pragma unroll
            for (int ni = 0; ni < 4; ni++) {
                int c0 = warpN * 32 + ni * 8 + lg;
                bfr[ni][0] = Bs[buf][c0][kb + lq];
                bfr[ni][1] = Bs[buf][c0][kb + lq + 4];
            }
            #pragma unroll
            for (int mi = 0; mi < 4; mi++)
                #pragma unroll
                for (int ni = 0; ni < 4; ni++) {
                    float* c = acc[mi][ni];
                    asm volatile(
                        "mma.sync.aligned.m16n8k8.row.col.f32.tf32.tf32.f32 "
                        "{%0,%1,%2,%3}, {%4,%5,%6,%7}, {%8,%9}, {%0,%1,%2,%3};"
                        : "+f"(c[0]), "+f"(c[1]), "+f"(c[2]), "+f"(c[3])
                        : "r"(afr[mi][0]), "r"(afr[mi][1]),
                          "r"(afr[mi][2]), "r"(afr[mi][3]),
                          "r"(bfr[ni][0]), "r"(bfr[ni][1]));
                }
        }
        __syncthreads();
        buf = nbuf;
    }

    float* dstbuf = (bn < 2) ? g_feat : d_out;
    #pragma unroll
    for (int mi = 0; mi < 4; mi++) {
        int row = row0 + warpM * 64 + mi * 16 + lg;
        #pragma unroll
        for (int ni = 0; ni < 4; ni++) {
            int col = wrow0 + warpN * 32 + ni * 8 + 2 * lq;
            if (row < n)
                *(float2*)(dstbuf + (size_t)row * 256 + col)
                    = make_float2(acc[mi][ni][0], acc[mi][ni][1]);
            if (row + 8 < n)
                *(float2*)(dstbuf + (size_t)(row + 8) * 256 + col)
                    = make_float2(acc[mi][ni][2], acc[mi][ni][3]);
        }
    }
}

// ---------------- K3: el / er per node (warp per node) ---------------------
__global__ void __launch_bounds__(256) node_attn(
        const float* __restrict__ attn_l, const float* __restrict__ attn_r, int n) {
    __shared__ float sl[256], sr[256];
    int tid = threadIdx.x;
    sl[tid] = attn_l[tid];
    sr[tid] = attn_r[tid];
    __syncthreads();
    int node = blockIdx.x * 8 + (tid >> 5);
    if (node >= n) return;
    int lane = tid & 31;
    const float* f = g_feat + (size_t)node * 256;
    int base = lane * 8;
    float4 f0 = *(const float4*)(f + base);
    float4 f1 = *(const float4*)(f + base + 4);
    float fv[8] = {f0.x, f0.y, f0.z, f0.w, f1.x, f1.y, f1.z, f1.w};
    float pl = 0.f, pr = 0.f;
    #pragma unroll
    for (int i = 0; i < 8; i++) {
        pl += fv[i] * sl[base + i];
        pr += fv[i] * sr[base + i];
    }
    #pragma unroll
    for (int off = 4; off; off >>= 1) {
        pl += __shfl_down_sync(0xffffffffu, pl, off, 8);
        pr += __shfl_down_sync(0xffffffffu, pr, off, 8);
    }
    if ((lane & 7) == 0) {
        int h = lane >> 3;
        g_el[node * HH + h] = pl;
        g_er[node * HH + h] = pr;
    }
}

// ---------------- CSR build: hist -> scan (cursor = rowptr) ----------------
__global__ void hist_kernel(const int* __restrict__ dst, int ne) {
    int e = blockIdx.x * blockDim.x + threadIdx.x;
    if (e < ne) atomicAdd(&g_cursor[dst[e]], 1);
}

__global__ void scan1(int n) {                 // block partial sums
    __shared__ int s[256];
    int idx = blockIdx.x * 256 + threadIdx.x;
    s[threadIdx.x] = (idx < n) ? g_cursor[idx] : 0;
    __syncthreads();
    for (int off = 128; off; off >>= 1) {
        if (threadIdx.x < off) s[threadIdx.x] += s[threadIdx.x + off];
        __syncthreads();
    }
    if (threadIdx.x == 0) g_blocksum[blockIdx.x] = s[0];
}

__global__ void scan2(int nb, int n) {         // exclusive scan of block sums
    __shared__ int s[256];
    int t = threadIdx.x;
    int v = (t < nb) ? g_blocksum[t] : 0;
    s[t] = v; __syncthreads();
    for (int off = 1; off < 256; off <<= 1) {
        int x = (t >= off) ? s[t - off] : 0;
        __syncthreads();
        s[t] += x;
        __syncthreads();
    }
    g_blocksum[t] = s[t] - v;                  // exclusive offset per block
    if (t == nb - 1) g_rowptr[n] = s[t];       // total = NE
}

__global__ void scan3(int n) {                 // final rowptr + cursor init
    __shared__ int s[256];
    int t = threadIdx.x;
    int idx = blockIdx.x * 256 + t;
    int v = (idx < n) ? g_cursor[idx] : 0;
    s[t] = v; __syncthreads();
    for (int off = 1; off < 256; off <<= 1) {
        int x = (t >= off) ? s[t - off] : 0;
        __syncthreads();
        s[t] += x;
        __syncthreads();
    }
    if (idx < n) {
        int val = g_blocksum[blockIdx.x] + s[t] - v;
        g_rowptr[idx] = val;
        g_cursor[idx] = val;
    }
}

// ---------------- K4: ee dot + scatter to CSR slot (GEMM-independent) ------
// Warp per edge; 8-lane group g handles head g. Lane 0 claims the CSR slot.
// Writes ONLY ee (edge term) + src id; el/er/leaky finish happens in K6.
__global__ void __launch_bounds__(256) ee_scatter(
        const float* __restrict__ ef, const int* __restrict__ src,
        const int* __restrict__ dst, int ne) {
    __shared__ float sv[HH][68];
    int tid = threadIdx.x;
    sv[tid >> 6][tid & 63] = g_v[tid];
    __syncthreads();
    int e = blockIdx.x * 8 + (tid >> 5);
    if (e >= ne) return;
    int lane = tid & 31;
    int g = lane >> 3, s = lane & 7;
    int sn = src[e], dn = dst[e];
    const float* erow = ef + (size_t)e * F_EDGE + s * 8;
    float4 a0 = *(const float4*)erow;
    float4 a1 = *(const float4*)(erow + 4);
    const float* vv = &sv[g][s * 8];
    float p = a0.x * vv[0] + a0.y * vv[1] + a0.z * vv[2] + a0.w * vv[3]
            + a1.x * vv[4] + a1.y * vv[5] + a1.z * vv[6] + a1.w * vv[7];
    #pragma unroll
    for (int off = 4; off; off >>= 1)
        p += __shfl_down_sync(0xffffffffu, p, off, 8);
    int pos = 0;
    if (lane == 0) pos = atomicAdd(&g_cursor[dn], 1);
    pos = __shfl_sync(0xffffffffu, pos, 0);
    if (s == 0)                                 // lanes 0,8,16,24: heads 0..3
        g_es[(size_t)pos * HH + g] = p;
    if (lane == 1) g_srcs[pos] = sn;
}

// ---------------- K6: logits finish + softmax + aggregate + residual -------
// Warp per dst node. Pass 1: ev = leaky(ee + el[src] + er[node]); write back;
// track per-head max. Pass 2: exp/denom/aggregate. ZERO atomics.
__global__ void __launch_bounds__(256) node_aggregate(
        float* __restrict__ out, int n) {
    int tid = threadIdx.x;
    int node = blockIdx.x * 8 + (tid >> 5);
    if (node >= n) return;
    int lane = tid & 31;
    int beg = g_rowptr[node], end = g_rowptr[node + 1];
    int deg = end - beg;
    if (deg == 0) return;                       // out already holds res

    // pass 1: finish logits + per-head maxima
    float4 er4 = *(const float4*)&g_er[node * HH];   // uniform per warp
    float m0 = -CUDART_INF_F, m1 = m0, m2 = m0, m3 = m0;
    for (int j = beg + lane; j < end; j += 32) {
        float4 ee = ((const float4*)g_es)[j];
        int sn = g_srcs[j];
        float4 el = *(const float4*)&g_el[sn * HH];
        float4 ev;
        ev.x = ee.x + el.x + er4.x;
        ev.y = ee.y + el.y + er4.y;
        ev.z = ee.z + el.z + er4.z;
        ev.w = ee.w + el.w + er4.w;
        ev.x = (ev.x > 0.f) ? ev.x : NEG_SLOPE * ev.x;
        ev.y = (ev.y > 0.f) ? ev.y : NEG_SLOPE * ev.y;
        ev.z = (ev.z > 0.f) ? ev.z : NEG_SLOPE * ev.z;
        ev.w = (ev.w > 0.f) ? ev.w : NEG_SLOPE * ev.w;
        ((float4*)g_es)[j] = ev;
        m0 = fmaxf(m0, ev.x); m1 = fmaxf(m1, ev.y);
        m2 = fmaxf(m2, ev.z); m3 = fmaxf(m3, ev.w);
    }
    __syncwarp();
    #pragma unroll
    for (int off = 16; off; off >>= 1) {
        m0 = fmaxf(m0, __shfl_xor_sync(0xffffffffu, m0, off));
        m1 = fmaxf(m1, __shfl_xor_sync(0xffffffffu, m1, off));
        m2 = fmaxf(m2, __shfl_xor_sync(0xffffffffu, m2, off));
        m3 = fmaxf(m3, __shfl_xor_sync(0xffffffffu, m3, off));
    }
    float mym = (lane == 0) ? m0 : (lane == 1) ? m1 : (lane == 2) ? m2 : m3;

    // pass 2: accumulate (4-edge unroll for load-latency overlap)
    float acc[8] = {};
    float denom = 0.f;                          // valid on lanes 0..3
    const int hsel = lane >> 3;                 // head source lane (0..3)
    int j = beg;
    for (; j + 3 < end; j += 4) {
        int sn0 = g_srcs[j],     sn1 = g_srcs[j + 1];
        int sn2 = g_srcs[j + 2], sn3 = g_srcs[j + 3];
        float ex0 = 0.f, ex1 = 0.f, ex2 = 0.f, ex3 = 0.f;
        if (lane < 4) {
            ex0 = __expf(g_es[(size_t)j * HH + lane] - mym);
            ex1 = __expf(g_es[(size_t)(j + 1) * HH + lane] - mym);
            ex2 = __expf(g_es[(size_t)(j + 2) * HH + lane] - mym);
            ex3 = __expf(g_es[(size_t)(j + 3) * HH + lane] - mym);
            denom += (ex0 + ex1) + (ex2 + ex3);
        }
        float ah0 = __shfl_sync(0xffffffffu, ex0, hsel);
        float ah1 = __shfl_sync(0xffffffffu, ex1, hsel);
        float ah2 = __shfl_sync(0xffffffffu, ex2, hsel);
        float ah3 = __shfl_sync(0xffffffffu, ex3, hsel);
        const float4* f0 = (const float4*)(g_feat + (size_t)sn0 * 256) + lane * 2;
        const float4* f1 = (const float4*)(g_feat + (size_t)sn1 * 256) + lane * 2;
        const float4* f2 = (const float4*)(g_feat + (size_t)sn2 * 256) + lane * 2;
        const float4* f3 = (const float4*)(g_feat + (size_t)sn3 * 256) + lane * 2;
        float4 a0 = f0[0], b0 = f0[1];
        float4 a1 = f1[0], b1 = f1[1];
        float4 a2 = f2[0], b2 = f2[1];
        float4 a3 = f3[0], b3 = f3[1];
        acc[0] += ah0 * a0.x + ah1 * a1.x + ah2 * a2.x + ah3 * a3.x;
        acc[1] += ah0 * a0.y + ah1 * a1.y + ah2 * a2.y + ah3 * a3.y;
        acc[2] += ah0 * a0.z + ah1 * a1.z + ah2 * a2.z + ah3 * a3.z;
        acc[3] += ah0 * a0.w + ah1 * a1.w + ah2 * a2.w + ah3 * a3.w;
        acc[4] += ah0 * b0.x + ah1 * b1.x + ah2 * b2.x + ah3 * b3.x;
        acc[5] += ah0 * b0.y + ah1 * b1.y + ah2 * b2.y + ah3 * b3.y;
        acc[6] += ah0 * b0.z + ah1 * b1.z + ah2 * b2.z + ah3 * b3.z;
        acc[7] += ah0 * b0.w + ah1 * b1.w + ah2 * b2.w + ah3 * b3.w;
    }
    for (; j < end; j++) {
        int sn = g_srcs[j];
        float ex = 0.f;
        if (lane < 4) {
            ex = __expf(g_es[(size_t)j * HH + lane] - mym);
            denom += ex;
        }
        float ah = __shfl_sync(0xffffffffu, ex, hsel);
        const float4* f = (const float4*)(g_feat + (size_t)sn * 256) + lane * 2;
        float4 a = f[0], b = f[1];
        acc[0] += ah * a.x; acc[1] += ah * a.y;
        acc[2] += ah * a.z; acc[3] += ah * a.w;
        acc[4] += ah * b.x; acc[5] += ah * b.y;
        acc[6] += ah * b.z; acc[7] += ah * b.w;
    }
    float dh = __shfl_sync(0xffffffffu, denom, hsel);
    float inv = 1.0f / (dh * (float)deg);
    float* p = out + (size_t)node * 256 + lane * 8;
    float4 o0 = *(float4*)p, o1 = *(float4*)(p + 4);
    o0.x += acc[0] * inv; o0.y += acc[1] * inv;
    o0.z += acc[2] * inv; o0.w += acc[3] * inv;
    o1.x += acc[4] * inv; o1.y += acc[5] * inv;
    o1.z += acc[6] * inv; o1.w += acc[7] * inv;
    *(float4*)p = o0; *(float4*)(p + 4) = o1;
}

// ---------------- launch ---------------------------------------------------
extern "C" void kernel_launch(void* const* d_in, const int* in_sizes, int n_in,
                              void* d_out, int out_size) {
    const float* h    = (const float*)d_in[0];
    const float* ef   = (const float*)d_in[1];
    const int*   src  = (const int*)d_in[2];
    const int*   dst  = (const int*)d_in[3];
    const float* Wfc  = (const float*)d_in[4];
    const float* We   = (const float*)d_in[5];
    const float* Wres = (const float*)d_in[6];
    const float* al   = (const float*)d_in[7];
    const float* ar   = (const float*)d_in[8];
    const float* ae   = (const float*)d_in[9];
    float* out = (float*)d_out;

    int n  = in_sizes[0] / F_IN;   // 50000
    int ne = in_sizes[2];          // 800000
    int nb = (n + 255) / 256;      // scan blocks (<=256)

    // Lazy one-time stream/event creation (host-side, no device allocation).
    static cudaStream_t s2 = nullptr, s3 = nullptr;
    static cudaEvent_t ev_fork = nullptr, ev_join = nullptr, ev_res = nullptr;
    if (s2 == nullptr) {
        cudaStreamCreateWithFlags(&s2, cudaStreamNonBlocking);
        cudaStreamCreateWithFlags(&s3, cudaStreamNonBlocking);
        cudaEventCreateWithFlags(&ev_fork, cudaEventDisableTiming);
        cudaEventCreateWithFlags(&ev_join, cudaEventDisableTiming);
        cudaEventCreateWithFlags(&ev_res, cudaEventDisableTiming);
    }

    void* pcur;
    cudaGetSymbolAddress(&pcur, g_cursor);

    // Fork both side streams off stream 0.
    cudaEventRecord(ev_fork, 0);
    cudaStreamWaitEvent(s2, ev_fork, 0);
    cudaStreamWaitEvent(s3, ev_fork, 0);

    // side chain (s2): CSR over dst, then ee dot + scatter (GEMM-independent)
    cudaMemsetAsync(pcur, 0, sizeof(int) * (size_t)n, s2);
    compute_ve<<<1, 256, 0, s2>>>(We, ae);
    hist_kernel<<<(ne + 255) / 256, 256, 0, s2>>>(dst, ne);
    scan1<<<nb, 256, 0, s2>>>(n);
    scan2<<<1, 256, 0, s2>>>(nb, n);
    scan3<<<nb, 256, 0, s2>>>(n);
    ee_scatter<<<(ne + 7) / 8, 256, 0, s2>>>(ef, src, dst, ne);
    cudaEventRecord(ev_join, s2);

    // side chain (s3): res GEMM -> d_out (independent until node_aggregate)
    dim3 gg((n + 127) / 128, 2);
    fused_gemm_tc<<<gg, 256, 0, s3>>>(h, Wfc, Wres, out, n, 2);
    cudaEventRecord(ev_res, s3);

    // main chain (stream 0): feat GEMM -> node_attn
    fused_gemm_tc<<<gg, 256>>>(h, Wfc, Wres, out, n, 0);
    node_attn<<<(n + 7) / 8, 256>>>(al, ar, n);

    // Join: aggregation needs ee/srcs/rowptr (s2), res in d_out (s3),
    // el/er/feat (s0).
    cudaStreamWaitEvent(0, ev_join, 0);
    cudaStreamWaitEvent(0, ev_res, 0);
    node_aggregate<<<(n + 7) / 8, 256>>>(out, n);
}